// round 4
// baseline (speedup 1.0000x reference)
#include <cuda_runtime.h>
#include <math.h>

#define BB 8
#define TT 2048
#define II 1024
#define HH 1024
#define G4 4096
#define OO 4096
#define NB 128

// ---------------- scratch (no allocations allowed) ----------------
__device__ float g_xg[(size_t)BB * TT * G4];   // [b][t][4H] input-gate precompute
// h messages: slot s, producer p -> 64 floats (pair layout over p's 8 cols x 8 b).
// Global pair-layout index (k>>1)*16 + b*2 + (k&1) == p*64 + local, p = k>>3.
__device__ float g_hmsg[2][NB][64];            // 256B per producer per slot
__device__ unsigned int g_tag[2][NB][32];      // one 128B line per producer per slot

// packed f32x2 helpers (sm_103a: fma.rn.f32x2 only reachable via PTX)
#define FMA2(d, a, b) asm("fma.rn.f32x2 %0, %1, %2, %0;" : "+l"(d) : "l"(a), "l"(b))
#define PACK2(d, s)   asm("mov.b64 %0, {%1, %1};" : "=l"(d) : "f"(s))

__device__ __forceinline__ float tanh_fast(float x) {
    float y; asm("tanh.approx.f32 %0, %1;" : "=f"(y) : "f"(x)); return y;
}
__device__ __forceinline__ float sigmoid_fast(float x) {
    return 0.5f + 0.5f * tanh_fast(0.5f * x);
}
__device__ __forceinline__ unsigned int ld_acq(const unsigned int* p) {
    unsigned int v;
    asm volatile("ld.acquire.gpu.u32 %0, [%1];" : "=r"(v) : "l"(p) : "memory");
    return v;
}
__device__ __forceinline__ void st_rel(unsigned int* p, unsigned int v) {
    asm volatile("st.release.gpu.u32 [%0], %1;" :: "l"(p), "r"(v) : "memory");
}

// =================================================================
// Kernel 1: xg = x @ W_ih^T + (b_ih+b_hh)   (unchanged from R1)
// =================================================================
#define BM 128
#define BN 128
#define BK 16
#define LDP 132

__global__ __launch_bounds__(256) void gemm_xg_kernel(
    const float* __restrict__ x, const float* __restrict__ Wih,
    const float* __restrict__ bih, const float* __restrict__ bhh)
{
    __shared__ float As[BK][LDP];
    __shared__ float Ws[BK][LDP];
    const int tid = threadIdx.x;
    const int m0 = blockIdx.y * BM;
    const int n0 = blockIdx.x * BN;
    const int tx = tid & 15;
    const int ty = tid >> 4;

    unsigned long long acc[4][8];
#pragma unroll
    for (int p = 0; p < 4; p++)
#pragma unroll
        for (int n = 0; n < 8; n++) acc[p][n] = 0ull;

    for (int k0 = 0; k0 < II; k0 += BK) {
#pragma unroll
        for (int r = 0; r < 2; r++) {
            int f = tid + r * 256;
            int m = f >> 2, kq = f & 3;
            float4 v = *(const float4*)&x[(size_t)(m0 + m) * II + k0 + kq * 4];
            As[kq * 4 + 0][m] = v.x;
            As[kq * 4 + 1][m] = v.y;
            As[kq * 4 + 2][m] = v.z;
            As[kq * 4 + 3][m] = v.w;
        }
#pragma unroll
        for (int r = 0; r < 2; r++) {
            int f = tid + r * 256;
            int n = f >> 2, kq = f & 3;
            float4 v = *(const float4*)&Wih[(size_t)(n0 + n) * II + k0 + kq * 4];
            Ws[kq * 4 + 0][n] = v.x;
            Ws[kq * 4 + 1][n] = v.y;
            Ws[kq * 4 + 2][n] = v.z;
            Ws[kq * 4 + 3][n] = v.w;
        }
        __syncthreads();
#pragma unroll
        for (int kk = 0; kk < BK; kk++) {
            const ulonglong2 a01 = *(const ulonglong2*)&As[kk][ty * 8];
            const ulonglong2 a23 = *(const ulonglong2*)&As[kk][ty * 8 + 4];
            const float4 w0 = *(const float4*)&Ws[kk][tx * 8];
            const float4 w1 = *(const float4*)&Ws[kk][tx * 8 + 4];
            unsigned long long wd[8];
            PACK2(wd[0], w0.x); PACK2(wd[1], w0.y);
            PACK2(wd[2], w0.z); PACK2(wd[3], w0.w);
            PACK2(wd[4], w1.x); PACK2(wd[5], w1.y);
            PACK2(wd[6], w1.z); PACK2(wd[7], w1.w);
#pragma unroll
            for (int n = 0; n < 8; n++) {
                FMA2(acc[0][n], a01.x, wd[n]);
                FMA2(acc[1][n], a01.y, wd[n]);
                FMA2(acc[2][n], a23.x, wd[n]);
                FMA2(acc[3][n], a23.y, wd[n]);
            }
        }
        __syncthreads();
    }

    float bias[8];
#pragma unroll
    for (int n = 0; n < 8; n++) {
        int nn = n0 + tx * 8 + n;
        bias[n] = bih[nn] + bhh[nn];
    }
#pragma unroll
    for (int p = 0; p < 4; p++) {
        float r0[8], r1[8];
#pragma unroll
        for (int n = 0; n < 8; n++) {
            float2 f = *(float2*)&acc[p][n];
            r0[n] = f.x + bias[n];
            r1[n] = f.y + bias[n];
        }
        const size_t m = (size_t)(m0 + ty * 8 + 2 * p);
        float* o0 = &g_xg[m * G4 + n0 + tx * 8];
        float* o1 = o0 + G4;
        *(float4*)o0       = make_float4(r0[0], r0[1], r0[2], r0[3]);
        *((float4*)o0 + 1) = make_float4(r0[4], r0[5], r0[6], r0[7]);
        *(float4*)o1       = make_float4(r1[0], r1[1], r1[2], r1[3]);
        *((float4*)o1 + 1) = make_float4(r1[4], r1[5], r1[6], r1[7]);
    }
}

// =================================================================
// Kernel 2: persistent recurrent LSTM. 128 CTAs x 256 thr, 1 CTA/SM.
//   Barrier-free: tagged 256B h-messages, per-lane acquire polling.
//   Step t (t>=1): poll tag[slot=t&1][p] == t for my warp's 16
//   producers, copy each piece to smem as soon as ready, dot, tail,
//   publish my piece into slot (t+1)&1 with release-tag t+1.
//   Anti-dependency on slot reuse: tag t from producer p implies p
//   finished reading slot (t-1)&1 (program order + bar + release),
//   and (t+1)&1 == (t-1)&1, so overwrite after observing all tags
//   is safe. Replay-safe: skew <= 1 step means stale final tags are
//   overwritten (t=0/1) long before any poll could alias them.
// =================================================================
#define CPB 8     // h columns per block
#define KC 128    // k elements per warp

__global__ __launch_bounds__(256, 1) void lstm_rec_kernel(const float* __restrict__ Whh)
{
    __shared__ float h_s[HH * BB];          // 32 KB, global pair layout
    __shared__ float part[8][32][9];        // [warp][local row][b], pad 9
    __shared__ float c_s[CPB][BB];          // cell state

    const int tid = threadIdx.x;
    const int w = tid >> 5;
    const int l = tid & 31;                          // lane
    const int bid = blockIdx.x;
    const int c0 = bid * CPB;
    const int grow = (l >> 3) * HH + c0 + (l & 7);   // global gate row
    const int kb = w * KC;

    // Pre-packed weight pairs
    unsigned long long wp[KC / 2];
    {
        const ulonglong2* src = (const ulonglong2*)&Whh[(size_t)grow * HH + kb];
#pragma unroll
        for (int i = 0; i < KC / 4; i++) {
            ulonglong2 v = src[i];
            wp[2 * i] = v.x;
            wp[2 * i + 1] = v.y;
        }
    }

    if (tid < CPB * BB) c_s[tid >> 3][tid & 7] = 0.f;
    __syncthreads();

    // reduce-thread identity + xg base pointer
    const int rcc = tid >> 3, rb8 = tid & 7;
    const float* xg_base = &g_xg[((size_t)rb8 * TT) * G4 + c0 + rcc];

    // message-staging identity: 2 lanes per producer, 8 float4 each
    const int pr = w * 16 + (l & 15);       // producer this lane serves
    const int half = l >> 4;                // which 128B half

    for (int t = 0; t < TT; t++) {
        const int rs = t & 1;               // read slot
        const int ws = rs ^ 1;              // write slot

        // ---- prefetch this step's xg gate biases (reduce threads) ----
        float xg0, xg1, xg2, xg3;
        if (tid < CPB * BB) {
            const float* p = xg_base + (size_t)t * G4;
            xg0 = __ldcs(p);
            xg1 = __ldcs(p + HH);
            xg2 = __ldcs(p + 2 * HH);
            xg3 = __ldcs(p + 3 * HH);
        }

        // ---- acquire-poll my producer's tag, copy its piece to smem ----
        if (t == 0) {
#pragma unroll
            for (int i = l; i < 256; i += 32)
                ((float4*)&h_s[kb * 8])[i] = make_float4(0.f, 0.f, 0.f, 0.f);
        } else {
            while (ld_acq(&g_tag[rs][pr][0]) != (unsigned int)t) { }
            const float4* src = (const float4*)g_hmsg[rs][pr] + half * 8;
            float4* dst = (float4*)&h_s[pr * 64] + half * 8;
#pragma unroll
            for (int i = 0; i < 8; i++) dst[i] = __ldcg(src + i);
        }
        __syncwarp();

        // ---- f32x2 dot partials: row l, k in [kb,kb+128), 8 batches ----
        unsigned long long acc[BB];
#pragma unroll
        for (int b = 0; b < BB; b++) acc[b] = 0ull;

        const float* hbase = &h_s[kb * 8];
#pragma unroll
        for (int jp = 0; jp < KC / 2; jp++) {
            const ulonglong2 h01 = *(const ulonglong2*)&hbase[jp * 16];
            const ulonglong2 h23 = *(const ulonglong2*)&hbase[jp * 16 + 4];
            const ulonglong2 h45 = *(const ulonglong2*)&hbase[jp * 16 + 8];
            const ulonglong2 h67 = *(const ulonglong2*)&hbase[jp * 16 + 12];
            const unsigned long long wv = wp[jp];
            FMA2(acc[0], wv, h01.x); FMA2(acc[1], wv, h01.y);
            FMA2(acc[2], wv, h23.x); FMA2(acc[3], wv, h23.y);
            FMA2(acc[4], wv, h45.x); FMA2(acc[5], wv, h45.y);
            FMA2(acc[6], wv, h67.x); FMA2(acc[7], wv, h67.y);
        }
#pragma unroll
        for (int b = 0; b < BB; b++) {
            float2 f = *(float2*)&acc[b];
            part[w][l][b] = f.x + f.y;
        }
        __syncthreads();

        // ---- gate reduce + MUFU nonlin + state update (64 threads) ----
        if (tid < CPB * BB) {
            float g0 = xg0, g1 = xg1, g2 = xg2, g3 = xg3;
#pragma unroll
            for (int ww = 0; ww < 8; ww++) {
                g0 += part[ww][0 * 8 + rcc][rb8];
                g1 += part[ww][1 * 8 + rcc][rb8];
                g2 += part[ww][2 * 8 + rcc][rb8];
                g3 += part[ww][3 * 8 + rcc][rb8];
            }
            const float ig = sigmoid_fast(g0);
            const float fg = sigmoid_fast(g1);
            const float gg = tanh_fast(g2);
            const float og = sigmoid_fast(g3);
            const float c = fg * c_s[rcc][rb8] + ig * gg;
            c_s[rcc][rb8] = c;
            const float h = og * tanh_fast(c);
            // publish into my message slot (pair layout within my 8 cols)
            g_hmsg[ws][bid][(rcc >> 1) * 16 + rb8 * 2 + (rcc & 1)] = h;
        }
        __syncthreads();   // all 64 h-values of this CTA written

        // ---- release-tag my piece (single hop; consumers poll it) ----
        if (tid == 0) {
            __threadfence();
            st_rel(&g_tag[ws][bid][0], (unsigned int)(t + 1));
        }
    }
}

// =================================================================
// Kernel 3: out[b][o] = sum_k hT[b][k]*W_fc[o][k] + b_fc[o]
//   hT = g_hmsg[0] flat (slot 0 tagged 2048), global pair layout.
// =================================================================
__global__ __launch_bounds__(256) void fc_kernel(
    const float* __restrict__ Wfc, const float* __restrict__ bfc,
    float* __restrict__ out)
{
    const float* hT = &g_hmsg[0][0][0];
    const int o = blockIdx.x;
    const int tid = threadIdx.x;
    float acc[BB];
#pragma unroll
    for (int b = 0; b < BB; b++) acc[b] = 0.f;

    for (int k = tid; k < HH; k += 256) {
        const float wv = Wfc[(size_t)o * HH + k];
        const int base = (k >> 1) * 16 + (k & 1);
#pragma unroll
        for (int b = 0; b < BB; b++) acc[b] += wv * hT[base + b * 2];
    }
    const int lane = tid & 31, wrp = tid >> 5;
#pragma unroll
    for (int off = 16; off; off >>= 1)
#pragma unroll
        for (int b = 0; b < BB; b++)
            acc[b] += __shfl_down_sync(0xffffffffu, acc[b], off);

    __shared__ float red[8][BB];
    if (lane == 0)
#pragma unroll
        for (int b = 0; b < BB; b++) red[wrp][b] = acc[b];
    __syncthreads();
    if (tid < BB) {
        float s = bfc[o];
#pragma unroll
        for (int ww = 0; ww < 8; ww++) s += red[ww][tid];
        out[(size_t)tid * OO + o] = s;
    }
}

// =================================================================
extern "C" void kernel_launch(void* const* d_in, const int* in_sizes, int n_in,
                              void* d_out, int out_size)
{
    const float* x    = (const float*)d_in[0];
    const float* Wih  = (const float*)d_in[1];
    const float* Whh  = (const float*)d_in[2];
    const float* bih  = (const float*)d_in[3];
    const float* bhh  = (const float*)d_in[4];
    const float* Wfc  = (const float*)d_in[5];
    const float* bfc  = (const float*)d_in[6];
    float* out = (float*)d_out;

    dim3 g1(G4 / BN, (BB * TT) / BM);
    gemm_xg_kernel<<<g1, 256>>>(x, Wih, bih, bhh);
    lstm_rec_kernel<<<NB, 256>>>(Whh);
    fc_kernel<<<OO, 256>>>(Wfc, bfc, out);
    (void)in_sizes; (void)n_in; (void)out_size;
}

// round 5
// speedup vs baseline: 1.7756x; 1.7756x over previous
#include <cuda_runtime.h>
#include <math.h>

#define BB 8
#define TT 2048
#define II 1024
#define HH 1024
#define G4 4096
#define OO 4096
#define NB 128

// ---------------- scratch (no allocations allowed) ----------------
__device__ float g_xg[(size_t)BB * TT * G4];   // [b][t][4H] input-gate precompute
__device__ float g_h[2][HH * BB];              // double-buffered h, PAIR layout:
                                               //   (k,b) -> (k>>1)*16 + b*2 + (k&1)
__device__ volatile unsigned int g_flags[NB * 32];  // one 128B line per CTA
__device__ volatile unsigned int g_sense;

// packed f32x2 helpers (sm_103a: fma.rn.f32x2 only reachable via PTX)
#define FMA2(d, a, b) asm("fma.rn.f32x2 %0, %1, %2, %0;" : "+l"(d) : "l"(a), "l"(b))
#define PACK2(d, s)   asm("mov.b64 %0, {%1, %1};" : "=l"(d) : "f"(s))

__device__ __forceinline__ float tanh_fast(float x) {
    float y; asm("tanh.approx.f32 %0, %1;" : "=f"(y) : "f"(x)); return y;
}
__device__ __forceinline__ float sigmoid_fast(float x) {
    return 0.5f + 0.5f * tanh_fast(0.5f * x);
}

// =================================================================
// Kernel 1: xg = x @ W_ih^T + (b_ih+b_hh).  2 CTAs/SM this round.
// =================================================================
#define BM 128
#define BN 128
#define BK 16
#define LDP 132

__global__ __launch_bounds__(256, 2) void gemm_xg_kernel(
    const float* __restrict__ x, const float* __restrict__ Wih,
    const float* __restrict__ bih, const float* __restrict__ bhh)
{
    __shared__ float As[BK][LDP];
    __shared__ float Ws[BK][LDP];
    const int tid = threadIdx.x;
    const int m0 = blockIdx.y * BM;
    const int n0 = blockIdx.x * BN;
    const int tx = tid & 15;
    const int ty = tid >> 4;

    unsigned long long acc[4][8];
#pragma unroll
    for (int p = 0; p < 4; p++)
#pragma unroll
        for (int n = 0; n < 8; n++) acc[p][n] = 0ull;

    for (int k0 = 0; k0 < II; k0 += BK) {
#pragma unroll
        for (int r = 0; r < 2; r++) {
            int f = tid + r * 256;
            int m = f >> 2, kq = f & 3;
            float4 v = *(const float4*)&x[(size_t)(m0 + m) * II + k0 + kq * 4];
            As[kq * 4 + 0][m] = v.x;
            As[kq * 4 + 1][m] = v.y;
            As[kq * 4 + 2][m] = v.z;
            As[kq * 4 + 3][m] = v.w;
        }
#pragma unroll
        for (int r = 0; r < 2; r++) {
            int f = tid + r * 256;
            int n = f >> 2, kq = f & 3;
            float4 v = *(const float4*)&Wih[(size_t)(n0 + n) * II + k0 + kq * 4];
            Ws[kq * 4 + 0][n] = v.x;
            Ws[kq * 4 + 1][n] = v.y;
            Ws[kq * 4 + 2][n] = v.z;
            Ws[kq * 4 + 3][n] = v.w;
        }
        __syncthreads();
#pragma unroll
        for (int kk = 0; kk < BK; kk++) {
            const ulonglong2 a01 = *(const ulonglong2*)&As[kk][ty * 8];
            const ulonglong2 a23 = *(const ulonglong2*)&As[kk][ty * 8 + 4];
            const float4 w0 = *(const float4*)&Ws[kk][tx * 8];
            const float4 w1 = *(const float4*)&Ws[kk][tx * 8 + 4];
            unsigned long long wd[8];
            PACK2(wd[0], w0.x); PACK2(wd[1], w0.y);
            PACK2(wd[2], w0.z); PACK2(wd[3], w0.w);
            PACK2(wd[4], w1.x); PACK2(wd[5], w1.y);
            PACK2(wd[6], w1.z); PACK2(wd[7], w1.w);
#pragma unroll
            for (int n = 0; n < 8; n++) {
                FMA2(acc[0][n], a01.x, wd[n]);
                FMA2(acc[1][n], a01.y, wd[n]);
                FMA2(acc[2][n], a23.x, wd[n]);
                FMA2(acc[3][n], a23.y, wd[n]);
            }
        }
        __syncthreads();
    }

    float bias[8];
#pragma unroll
    for (int n = 0; n < 8; n++) {
        int nn = n0 + tx * 8 + n;
        bias[n] = bih[nn] + bhh[nn];
    }
#pragma unroll
    for (int p = 0; p < 4; p++) {
        float r0[8], r1[8];
#pragma unroll
        for (int n = 0; n < 8; n++) {
            float2 f = *(float2*)&acc[p][n];
            r0[n] = f.x + bias[n];
            r1[n] = f.y + bias[n];
        }
        const size_t m = (size_t)(m0 + ty * 8 + 2 * p);
        float* o0 = &g_xg[m * G4 + n0 + tx * 8];
        float* o1 = o0 + G4;
        *(float4*)o0       = make_float4(r0[0], r0[1], r0[2], r0[3]);
        *((float4*)o0 + 1) = make_float4(r0[4], r0[5], r0[6], r0[7]);
        *(float4*)o1       = make_float4(r1[0], r1[1], r1[2], r1[3]);
        *((float4*)o1 + 1) = make_float4(r1[4], r1[5], r1[6], r1[7]);
    }
}

// =================================================================
// Kernel 2: persistent recurrent LSTM. 128 CTAs x 512 thr, 1 CTA/SM.
//   16 warps, KC=64 k-elems each (same fma2 floor, 2x latency hiding).
//   Distributed-flag barrier with __nanosleep spins (DVFS-friendly).
// =================================================================
#define CPB 8     // h columns per block
#define KC 64     // k elements per warp
#define NW 16     // warps

__global__ __launch_bounds__(512, 1) void lstm_rec_kernel(const float* __restrict__ Whh)
{
    __shared__ float h_s[HH * BB];          // 32 KB, pair layout
    __shared__ float part[NW][32][9];       // [warp][local row][b], pad 9
    __shared__ float c_s[CPB][BB];          // cell state

    const int tid = threadIdx.x;
    const int w = tid >> 5;
    const int l = tid & 31;                          // local gate row
    const int bid = blockIdx.x;
    const int c0 = bid * CPB;
    const int grow = (l >> 3) * HH + c0 + (l & 7);   // global gate row
    const int kb = w * KC;

    // Pre-packed weight pairs: wp[jp] = (W[grow][kb+2jp], W[grow][kb+2jp+1])
    unsigned long long wp[KC / 2];
    {
        const ulonglong2* src = (const ulonglong2*)&Whh[(size_t)grow * HH + kb];
#pragma unroll
        for (int i = 0; i < KC / 4; i++) {
            ulonglong2 v = src[i];
            wp[2 * i] = v.x;
            wp[2 * i + 1] = v.y;
        }
    }

    if (tid < CPB * BB) c_s[tid >> 3][tid & 7] = 0.f;
    __syncthreads();

    // reduce-thread identity + xg base pointer
    const int rcc = tid >> 3, rb8 = tid & 7;
    const float* xg_base = &g_xg[((size_t)rb8 * TT) * G4 + c0 + rcc];

    // per-warp staging: own KC*8 floats = 2KB = 128 float4, 4/lane
    float4* hchunk = (float4*)&h_s[kb * 8];

    for (int t = 0; t < TT; t++) {
        const int rdbuf = t & 1;
        const int wrbuf = rdbuf ^ 1;

        // ---- prefetch this step's xg gate biases (reduce threads) ----
        float xg0, xg1, xg2, xg3;
        if (tid < CPB * BB) {
            const float* p = xg_base + (size_t)t * G4;
            xg0 = __ldcs(p);
            xg1 = __ldcs(p + HH);
            xg2 = __ldcs(p + 2 * HH);
            xg3 = __ldcs(p + 3 * HH);
        }

        // ---- per-warp stage of OWN h chunk (L2; warp reads only this) ----
        if (t == 0) {
#pragma unroll
            for (int i = l; i < 128; i += 32)
                hchunk[i] = make_float4(0.f, 0.f, 0.f, 0.f);
        } else {
            const float4* src = (const float4*)&g_h[rdbuf][kb * 8];
#pragma unroll
            for (int i = l; i < 128; i += 32)
                hchunk[i] = __ldcg(src + i);
        }
        __syncwarp();

        // ---- f32x2 dot partials: row l, k in [kb,kb+64), 8 batches ----
        unsigned long long acc[BB];
#pragma unroll
        for (int b = 0; b < BB; b++) acc[b] = 0ull;

        const float* hbase = &h_s[kb * 8];
#pragma unroll
        for (int jp = 0; jp < KC / 2; jp++) {
            const ulonglong2 h01 = *(const ulonglong2*)&hbase[jp * 16];
            const ulonglong2 h23 = *(const ulonglong2*)&hbase[jp * 16 + 4];
            const ulonglong2 h45 = *(const ulonglong2*)&hbase[jp * 16 + 8];
            const ulonglong2 h67 = *(const ulonglong2*)&hbase[jp * 16 + 12];
            const unsigned long long wv = wp[jp];
            FMA2(acc[0], wv, h01.x); FMA2(acc[1], wv, h01.y);
            FMA2(acc[2], wv, h23.x); FMA2(acc[3], wv, h23.y);
            FMA2(acc[4], wv, h45.x); FMA2(acc[5], wv, h45.y);
            FMA2(acc[6], wv, h67.x); FMA2(acc[7], wv, h67.y);
        }
#pragma unroll
        for (int b = 0; b < BB; b++) {
            float2 f = *(float2*)&acc[b];
            part[w][l][b] = f.x + f.y;
        }
        __syncthreads();

        // ---- gate reduce + MUFU nonlin + state update (64 threads) ----
        if (tid < CPB * BB) {
            float g0 = xg0, g1 = xg1, g2 = xg2, g3 = xg3;
#pragma unroll
            for (int ww = 0; ww < NW; ww++) {
                g0 += part[ww][0 * 8 + rcc][rb8];
                g1 += part[ww][1 * 8 + rcc][rb8];
                g2 += part[ww][2 * 8 + rcc][rb8];
                g3 += part[ww][3 * 8 + rcc][rb8];
            }
            const float ig = sigmoid_fast(g0);
            const float fg = sigmoid_fast(g1);
            const float gg = tanh_fast(g2);
            const float og = sigmoid_fast(g3);
            const float c = fg * c_s[rcc][rb8] + ig * gg;
            c_s[rcc][rb8] = c;
            const float h = og * tanh_fast(c);
            const int col = c0 + rcc;
            g_h[wrbuf][(col >> 1) * 16 + rb8 * 2 + (col & 1)] = h;
        }
        __syncthreads();   // h writes done CTA-wide

        // ---- grid barrier: distributed arrival, CTA0 collects, 1-word release.
        //      All spins use __nanosleep (HW sleep) to keep DVFS clocks up.
        const unsigned int tgt = (unsigned int)(t + 1);
        if (tid == 0) {
            __threadfence();
            g_flags[bid * 32] = tgt;
        }
        if (bid == 0) {
            if (tid < NB) {
                while (g_flags[tid * 32] != tgt) __nanosleep(32);
            }
            __syncthreads();
            if (tid == 0) {
                __threadfence();
                g_sense = tgt;
            }
        } else {
            if (tid == 0) {
                while (g_sense != tgt) __nanosleep(32);
                __threadfence();
            }
            __syncthreads();
        }
    }
}

// =================================================================
// Kernel 3: out[b][o] = sum_k hT[b][k]*W_fc[o][k] + b_fc[o]
//   hT in g_h[0] (pair layout) after 2048 steps.
// =================================================================
__global__ __launch_bounds__(256) void fc_kernel(
    const float* __restrict__ Wfc, const float* __restrict__ bfc,
    float* __restrict__ out)
{
    const int o = blockIdx.x;
    const int tid = threadIdx.x;
    float acc[BB];
#pragma unroll
    for (int b = 0; b < BB; b++) acc[b] = 0.f;

    for (int k = tid; k < HH; k += 256) {
        const float wv = Wfc[(size_t)o * HH + k];
        const int base = (k >> 1) * 16 + (k & 1);
#pragma unroll
        for (int b = 0; b < BB; b++) acc[b] += wv * g_h[0][base + b * 2];
    }
    const int lane = tid & 31, wrp = tid >> 5;
#pragma unroll
    for (int off = 16; off; off >>= 1)
#pragma unroll
        for (int b = 0; b < BB; b++)
            acc[b] += __shfl_down_sync(0xffffffffu, acc[b], off);

    __shared__ float red[8][BB];
    if (lane == 0)
#pragma unroll
        for (int b = 0; b < BB; b++) red[wrp][b] = acc[b];
    __syncthreads();
    if (tid < BB) {
        float s = bfc[o];
#pragma unroll
        for (int ww = 0; ww < 8; ww++) s += red[ww][tid];
        out[(size_t)tid * OO + o] = s;
    }
}

// =================================================================
extern "C" void kernel_launch(void* const* d_in, const int* in_sizes, int n_in,
                              void* d_out, int out_size)
{
    const float* x    = (const float*)d_in[0];
    const float* Wih  = (const float*)d_in[1];
    const float* Whh  = (const float*)d_in[2];
    const float* bih  = (const float*)d_in[3];
    const float* bhh  = (const float*)d_in[4];
    const float* Wfc  = (const float*)d_in[5];
    const float* bfc  = (const float*)d_in[6];
    float* out = (float*)d_out;

    dim3 g1(G4 / BN, (BB * TT) / BM);
    gemm_xg_kernel<<<g1, 256>>>(x, Wih, bih, bhh);
    lstm_rec_kernel<<<NB, 512>>>(Whh);
    fc_kernel<<<OO, 256>>>(Wfc, bfc, out);
    (void)in_sizes; (void)n_in; (void)out_size;
}